// round 5
// baseline (speedup 1.0000x reference)
#include <cuda_runtime.h>
#include <math_constants.h>

// ChamferLoss: B=8, N=M=4096, D=3, fp32 in, scalar fp32 out.
// d2' = -2*dot(q,r) + rsq   (qsq folded in AFTER the min)
// fma.rn.f32x2: 2 query points per FFMA2 (candidate coeffs duplicated in smem).
// PTS=8 queries/thread -> 0.25 LDS/point-eval; 16 warps/block on disjoint
// candidate slices -> 4096 warps (6.9/SMSP) to cover FFMA2 chain latency.

#define B_DIM  8
#define N_PTS  4096
#define TPB    512        // 16 warps
#define NSLICE 16         // one candidate slice per warp
#define PTS    8          // query points per thread (4 packed groups)
#define QPB    256        // queries per block (32 lanes * PTS)
#define TILE   1024       // candidates per shared tile
#define SLICE  (TILE / NSLICE)   // 64 candidates per warp per tile
#define EPS    1e-8f

typedef unsigned long long u64;

__device__ __forceinline__ u64 ffma2(u64 a, u64 b, u64 c) {
    u64 d;
    asm("fma.rn.f32x2 %0, %1, %2, %3;" : "=l"(d) : "l"(a), "l"(b), "l"(c));
    return d;
}
__device__ __forceinline__ u64 pack2(float lo, float hi) {
    u64 d;
    asm("mov.b64 %0, {%1, %2};" : "=l"(d) : "f"(lo), "f"(hi));
    return d;
}
__device__ __forceinline__ float2 unpack2(u64 v) {
    float2 f;
    asm("mov.b64 {%0, %1}, %2;" : "=f"(f.x), "=f"(f.y) : "l"(v));
    return f;
}

__global__ void zero_out_kernel(float* out) { out[0] = 0.0f; }

__global__ __launch_bounds__(TPB) void chamfer_kernel(
    const float* __restrict__ x1, const float* __restrict__ y1,
    float* __restrict__ out, float scale)
{
    // sA[i] = { (-2rx,-2rx), (-2ry,-2ry) }   sB[i] = { (-2rz,-2rz), (rsq,rsq) }
    __shared__ ulonglong2 sA[TILE];
    __shared__ ulonglong2 sB[TILE];
    __shared__ float sPart[NSLICE][QPB];   // [slice][q_local] partial mins
    __shared__ float sQsq[QPB];
    __shared__ float wsum[TPB / 32];

    const int b = blockIdx.y;
    const float* Q = (blockIdx.z == 0) ? x1 : y1;
    const float* R = (blockIdx.z == 0) ? y1 : x1;
    const float* Qb = Q + (size_t)b * N_PTS * 3;
    const float* Rb = R + (size_t)b * N_PTS * 3;

    const int tid = threadIdx.x;
    const int u   = tid & 31;    // lane: query sub-id
    const int s   = tid >> 5;    // warp: candidate slice
    const int qbase = blockIdx.x * QPB;

    // 8 query points per thread: q_local = u + k*32 (same for every warp)
    float qx[PTS], qy[PTS], qz[PTS], qsq[PTS];
    #pragma unroll
    for (int k = 0; k < PTS; ++k) {
        const int p = qbase + u + k * 32;
        qx[k] = Qb[p * 3 + 0];
        qy[k] = Qb[p * 3 + 1];
        qz[k] = Qb[p * 3 + 2];
        qsq[k] = fmaf(qx[k], qx[k], fmaf(qy[k], qy[k], qz[k] * qz[k]));
    }
    // packed query registers: group g = points (2g, 2g+1)
    u64 qX[4], qY[4], qZ[4];
    #pragma unroll
    for (int g = 0; g < 4; ++g) {
        qX[g] = pack2(qx[2 * g], qx[2 * g + 1]);
        qY[g] = pack2(qy[2 * g], qy[2 * g + 1]);
        qZ[g] = pack2(qz[2 * g], qz[2 * g + 1]);
    }

    float mn[PTS];
    #pragma unroll
    for (int k = 0; k < PTS; ++k) mn[k] = CUDART_INF_F;

    for (int base = 0; base < N_PTS; base += TILE) {
        // cooperative tile fill (2 candidates per thread)
        for (int i = tid; i < TILE; i += TPB) {
            const float* r = Rb + (size_t)(base + i) * 3;
            const float rx = r[0], ry = r[1], rz = r[2];
            const float rq = fmaf(rx, rx, fmaf(ry, ry, rz * rz));
            const float c0 = -2.0f * rx, c1 = -2.0f * ry, c2 = -2.0f * rz;
            sA[i] = make_ulonglong2(pack2(c0, c0), pack2(c1, c1));
            sB[i] = make_ulonglong2(pack2(c2, c2), pack2(rq, rq));
        }
        __syncthreads();

        // this warp's candidate slice within the tile
        const ulonglong2* __restrict__ pA = sA + s * SLICE;
        const ulonglong2* __restrict__ pB = sB + s * SLICE;

        #pragma unroll 4
        for (int j = 0; j < SLICE; ++j) {
            const ulonglong2 a = pA[j];   // (c0,c0),(c1,c1)
            const ulonglong2 c = pB[j];   // (c2,c2),(cr,cr)
            #pragma unroll
            for (int g = 0; g < 4; ++g) {
                u64 t = ffma2(c.x, qZ[g], c.y);
                t = ffma2(a.y, qY[g], t);
                t = ffma2(a.x, qX[g], t);
                const float2 f = unpack2(t);
                mn[2 * g]     = fminf(mn[2 * g],     f.x);
                mn[2 * g + 1] = fminf(mn[2 * g + 1], f.y);
            }
        }
        __syncthreads();
    }

    // publish partial mins; warp 0 publishes qsq
    #pragma unroll
    for (int k = 0; k < PTS; ++k) sPart[s][u + k * 32] = mn[k];
    if (s == 0) {
        #pragma unroll
        for (int k = 0; k < PTS; ++k) sQsq[u + k * 32] = qsq[k];
    }
    __syncthreads();

    // combine slices: threads 0..QPB-1 each own one query
    float v = 0.0f;
    if (tid < QPB) {
        float m = sPart[0][tid];
        #pragma unroll
        for (int ss = 1; ss < NSLICE; ++ss) m = fminf(m, sPart[ss][tid]);
        v = sqrtf(fmaxf(m + sQsq[tid], 0.0f) + EPS);
    }

    // block sum
    #pragma unroll
    for (int off = 16; off > 0; off >>= 1)
        v += __shfl_xor_sync(0xFFFFFFFFu, v, off);
    if (u == 0) wsum[s] = v;
    __syncthreads();
    if (tid == 0) {
        float total = 0.0f;
        #pragma unroll
        for (int w = 0; w < TPB / 32; ++w) total += wsum[w];
        atomicAdd(out, total * scale);
    }
}

extern "C" void kernel_launch(void* const* d_in, const int* in_sizes, int n_in,
                              void* d_out, int out_size)
{
    const float* x1 = (const float*)d_in[0];
    const float* y1 = (const float*)d_in[1];
    float* out = (float*)d_out;

    zero_out_kernel<<<1, 1>>>(out);

    dim3 grid(N_PTS / QPB, B_DIM, 2);   // (16, 8, 2) = 256 blocks x 16 warps = 4096 warps
    const float scale = 1.0f / (float)(B_DIM * N_PTS);
    chamfer_kernel<<<grid, TPB>>>(x1, y1, out, scale);
}

// round 6
// speedup vs baseline: 1.1276x; 1.1276x over previous
#include <cuda_runtime.h>
#include <math_constants.h>

// ChamferLoss fused-direction kernel.
// Each unique (x,y) pair evaluated ONCE: d2 = -2 x.y + (|x|^2 + |y|^2)
// -> 4 fma-pipe ops/pair (3 FFMA + 1 FADD) instead of 6 (two directions).
// xmin[q] kept in registers; ymin[c] in shared with rotating quad ownership
// (lane u owns candidate-quad (u+s)&31 at step s: race-free, no atomics).
// Cross-block combine via global atomicMin on int bits (d2 >= 0).

#define B_DIM  8
#define N_PTS  4096
#define TPB    256
#define NWARP  8
#define PTS    8                  // queries per thread
#define QPB    256                // queries per block
#define CSPLIT 4
#define CPB    (N_PTS / CSPLIT)   // 1024 candidates per block
#define CPW    (CPB / NWARP)      // 128 candidates per warp
#define NQUAD  (CPW / 4)          // 32 quads per warp
#define EPS    1e-8f

__device__ int g_xmin[B_DIM * N_PTS];
__device__ int g_ymin[B_DIM * N_PTS];

__global__ void init_kernel(float* out) {
    const int i = blockIdx.x * blockDim.x + threadIdx.x;
    if (i < B_DIM * N_PTS) {
        g_xmin[i] = 0x7F800000;   // +inf
        g_ymin[i] = 0x7F800000;
    }
    if (i == 0) out[0] = 0.0f;
}

__global__ __launch_bounds__(TPB, 3) void chamfer_main(
    const float* __restrict__ x1, const float* __restrict__ y1)
{
    __shared__ float4 sC[CPB];            // (-2ry... rsq) per candidate: 16KB
    __shared__ float  sY[CPB];            // ymin partials (warp-exclusive ranges)
    __shared__ float  sPart[NWARP][QPB];  // xmin partials

    const int b     = blockIdx.y;
    const int qbase = blockIdx.x * QPB;
    const int cbase = blockIdx.z * CPB;
    const float* Qb = x1 + (size_t)b * N_PTS * 3;
    const float* Rb = y1 + (size_t)b * N_PTS * 3;

    const int tid = threadIdx.x;
    const int u   = tid & 31;
    const int w   = tid >> 5;

    // tile fill: candidate record = (-2rx, -2ry, -2rz, rsq)
    for (int i = tid; i < CPB; i += TPB) {
        const float* r = Rb + (size_t)(cbase + i) * 3;
        const float rx = r[0], ry = r[1], rz = r[2];
        sC[i] = make_float4(-2.0f * rx, -2.0f * ry, -2.0f * rz,
                            fmaf(rx, rx, fmaf(ry, ry, rz * rz)));
        sY[i] = CUDART_INF_F;
    }

    // 8 queries per thread
    float qx[PTS], qy[PTS], qz[PTS], xsq[PTS], mn[PTS];
    #pragma unroll
    for (int k = 0; k < PTS; ++k) {
        const int p = qbase + u + k * 32;
        qx[k] = Qb[p * 3 + 0];
        qy[k] = Qb[p * 3 + 1];
        qz[k] = Qb[p * 3 + 2];
        xsq[k] = fmaf(qx[k], qx[k], fmaf(qy[k], qy[k], qz[k] * qz[k]));
        mn[k] = CUDART_INF_F;
    }
    __syncthreads();

    // rotating quad ownership: at step s, lane u owns quad (u+s)&31 of warp w's
    // 128-candidate slice. Converged warp => sequential steps => race-free sY rmw.
    const int wslice = w * CPW;
    for (int s = 0; s < NQUAD; ++s) {
        const int qd   = (u + s) & (NQUAD - 1);
        const int cidx = wslice + qd * 4;

        float4 C[4];
        #pragma unroll
        for (int c = 0; c < 4; ++c) C[c] = sC[cidx + c];

        float my[4];
        #pragma unroll
        for (int c = 0; c < 4; ++c) my[c] = sY[cidx + c];

        #pragma unroll
        for (int c = 0; c < 4; ++c) {
            const float c0 = C[c].x, c1 = C[c].y, c2 = C[c].z, rsq = C[c].w;
            float ml = my[c];
            #pragma unroll
            for (int k = 0; k < PTS; ++k) {
                const float S = xsq[k] + rsq;                       // 1 FADD
                float t = fmaf(c2, qz[k], S);                       // 3 FFMA
                t = fmaf(c1, qy[k], t);
                t = fmaf(c0, qx[k], t);
                mn[k] = fminf(mn[k], t);                            // 2 FMNMX (alu)
                ml    = fminf(ml, t);
            }
            my[c] = ml;
        }

        #pragma unroll
        for (int c = 0; c < 4; ++c) sY[cidx + c] = my[c];
    }

    // publish xmin partials
    #pragma unroll
    for (int k = 0; k < PTS; ++k) sPart[w][u + k * 32] = mn[k];
    __syncthreads();

    // combine xmin across warps -> global atomicMin (int bits, d2 >= ~0)
    {
        float m = sPart[0][tid];
        #pragma unroll
        for (int ww = 1; ww < NWARP; ++ww) m = fminf(m, sPart[ww][tid]);
        atomicMin(&g_xmin[b * N_PTS + qbase + tid], __float_as_int(m));
    }
    // ymin -> global atomicMin
    for (int i = tid; i < CPB; i += TPB)
        atomicMin(&g_ymin[b * N_PTS + cbase + i], __float_as_int(sY[i]));
}

__global__ void pass2_kernel(float* out, float scale) {
    __shared__ float wsum[8];
    const int i = blockIdx.x * blockDim.x + threadIdx.x;   // 0 .. 65535
    const int which = i >> 15;
    const int idx   = i & 32767;
    const float d2 = __int_as_float(which ? g_ymin[idx] : g_xmin[idx]);
    float v = sqrtf(fmaxf(d2, 0.0f) + EPS);

    #pragma unroll
    for (int off = 16; off > 0; off >>= 1)
        v += __shfl_xor_sync(0xFFFFFFFFu, v, off);

    const int u = threadIdx.x & 31;
    const int w = threadIdx.x >> 5;
    if (u == 0) wsum[w] = v;
    __syncthreads();
    if (threadIdx.x == 0) {
        float t = 0.0f;
        #pragma unroll
        for (int ww = 0; ww < 8; ++ww) t += wsum[ww];
        atomicAdd(out, t * scale);
    }
}

extern "C" void kernel_launch(void* const* d_in, const int* in_sizes, int n_in,
                              void* d_out, int out_size)
{
    const float* x1 = (const float*)d_in[0];
    const float* y1 = (const float*)d_in[1];
    float* out = (float*)d_out;

    init_kernel<<<(B_DIM * N_PTS + 255) / 256, 256>>>(out);

    dim3 grid(N_PTS / QPB, B_DIM, CSPLIT);   // (16, 8, 4) = 512 blocks
    chamfer_main<<<grid, TPB>>>(x1, y1);

    const float scale = 1.0f / (float)(B_DIM * N_PTS);
    pass2_kernel<<<(2 * B_DIM * N_PTS) / 256, 256>>>(out, scale);
}

// round 7
// speedup vs baseline: 1.3639x; 1.2096x over previous
#include <cuda_runtime.h>
#include <math_constants.h>

// ChamferLoss fused-direction kernel, no atomics / no init pass.
// Each unique (x,y) pair evaluated ONCE: d2 = -2 x.y + (|x|^2 + |y|^2)
// -> 4 fma-pipe ops/pair (3 FFMA + 1 FADD) + 2 FMNMX (alu).
// xmin[q] in registers; ymin[c] in shared via rotating quad ownership.
// Per-block partials go to exclusive __device__ slots (plain STG), pass2 reduces.

#define B_DIM  8
#define N_PTS  4096
#define TPB    256
#define NWARP  8
#define PTS    16                 // queries per thread
#define QPB    512                // queries per block (32 lanes * PTS)
#define NQB    (N_PTS / QPB)      // 8 query blocks
#define CSPLIT 4
#define CPB    (N_PTS / CSPLIT)   // 1024 candidates per block
#define CPW    (CPB / NWARP)      // 128 candidates per warp
#define NQUAD  (CPW / 4)          // 32 quads per warp
#define EPS    1e-8f

__device__ float g_xpart[CSPLIT][B_DIM][N_PTS];  // [z][b][q]
__device__ float g_ypart[NQB][B_DIM][N_PTS];     // [qb][b][c]

__global__ __launch_bounds__(TPB, 2) void chamfer_main(
    const float* __restrict__ x1, const float* __restrict__ y1,
    float* __restrict__ out)
{
    __shared__ float4 sC[CPB];            // (-2rx,-2ry,-2rz,rsq): 16KB
    __shared__ float  sY[CPB];            // ymin partials (warp-exclusive ranges)
    __shared__ float  sPart[NWARP][QPB];  // xmin partials: 16KB

    const int b     = blockIdx.y;
    const int qb    = blockIdx.x;
    const int qbase = qb * QPB;
    const int cbase = blockIdx.z * CPB;
    const float* Qb = x1 + (size_t)b * N_PTS * 3;
    const float* Rb = y1 + (size_t)b * N_PTS * 3;

    const int tid = threadIdx.x;
    const int u   = tid & 31;
    const int w   = tid >> 5;

    if (qb == 0 && b == 0 && blockIdx.z == 0 && tid == 0) out[0] = 0.0f;

    // tile fill: candidate record = (-2rx, -2ry, -2rz, rsq)
    for (int i = tid; i < CPB; i += TPB) {
        const float* r = Rb + (size_t)(cbase + i) * 3;
        const float rx = r[0], ry = r[1], rz = r[2];
        sC[i] = make_float4(-2.0f * rx, -2.0f * ry, -2.0f * rz,
                            fmaf(rx, rx, fmaf(ry, ry, rz * rz)));
        sY[i] = CUDART_INF_F;
    }

    // 16 queries per thread
    float qx[PTS], qy[PTS], qz[PTS], xsq[PTS], mn[PTS];
    #pragma unroll
    for (int k = 0; k < PTS; ++k) {
        const int p = qbase + u + k * 32;
        qx[k] = Qb[p * 3 + 0];
        qy[k] = Qb[p * 3 + 1];
        qz[k] = Qb[p * 3 + 2];
        xsq[k] = fmaf(qx[k], qx[k], fmaf(qy[k], qy[k], qz[k] * qz[k]));
        mn[k] = CUDART_INF_F;
    }
    __syncthreads();

    // rotating quad ownership: at step s, lane u owns quad (u+s)&31 of warp w's
    // 128-candidate slice. Converged warp => sequential steps => race-free sY rmw.
    const int wslice = w * CPW;
    for (int s = 0; s < NQUAD; ++s) {
        const int qd   = (u + s) & (NQUAD - 1);
        const int cidx = wslice + qd * 4;

        float4 C[4];
        #pragma unroll
        for (int c = 0; c < 4; ++c) C[c] = sC[cidx + c];

        float my[4];
        #pragma unroll
        for (int c = 0; c < 4; ++c) my[c] = sY[cidx + c];

        #pragma unroll
        for (int c = 0; c < 4; ++c) {
            const float c0 = C[c].x, c1 = C[c].y, c2 = C[c].z, rsq = C[c].w;
            float ml = my[c];
            #pragma unroll
            for (int k = 0; k < PTS; ++k) {
                const float S = xsq[k] + rsq;        // 1 FADD
                float t = fmaf(c2, qz[k], S);        // 3 FFMA
                t = fmaf(c1, qy[k], t);
                t = fmaf(c0, qx[k], t);
                mn[k] = fminf(mn[k], t);             // 2 FMNMX (alu)
                ml    = fminf(ml, t);
            }
            my[c] = ml;
        }

        #pragma unroll
        for (int c = 0; c < 4; ++c) sY[cidx + c] = my[c];
    }

    // publish xmin partials
    #pragma unroll
    for (int k = 0; k < PTS; ++k) sPart[w][u + k * 32] = mn[k];
    __syncthreads();

    // combine xmin across warps -> exclusive global slot (plain store)
    for (int q = tid; q < QPB; q += TPB) {
        float m = sPart[0][q];
        #pragma unroll
        for (int ww = 1; ww < NWARP; ++ww) m = fminf(m, sPart[ww][q]);
        g_xpart[blockIdx.z][b][qbase + q] = m;
    }
    // ymin -> exclusive global slot
    for (int i = tid; i < CPB; i += TPB)
        g_ypart[qb][b][cbase + i] = sY[i];
}

__global__ void pass2_kernel(float* out, float scale) {
    __shared__ float wsum[8];
    const int i = blockIdx.x * blockDim.x + threadIdx.x;   // 0 .. 65535
    float v;
    if (i < B_DIM * N_PTS) {
        // x side: min over CSPLIT partials
        const int b = i >> 12, q = i & 4095;
        float m = g_xpart[0][b][q];
        #pragma unroll
        for (int z = 1; z < CSPLIT; ++z) m = fminf(m, g_xpart[z][b][q]);
        v = sqrtf(fmaxf(m, 0.0f) + EPS);
    } else {
        // y side: min over NQB partials
        const int j = i - B_DIM * N_PTS;
        const int b = j >> 12, c = j & 4095;
        float m = g_ypart[0][b][c];
        #pragma unroll
        for (int z = 1; z < NQB; ++z) m = fminf(m, g_ypart[z][b][c]);
        v = sqrtf(fmaxf(m, 0.0f) + EPS);
    }

    #pragma unroll
    for (int off = 16; off > 0; off >>= 1)
        v += __shfl_xor_sync(0xFFFFFFFFu, v, off);

    const int u = threadIdx.x & 31;
    const int w = threadIdx.x >> 5;
    if (u == 0) wsum[w] = v;
    __syncthreads();
    if (threadIdx.x == 0) {
        float t = 0.0f;
        #pragma unroll
        for (int ww = 0; ww < 8; ++ww) t += wsum[ww];
        atomicAdd(out, t * scale);
    }
}

extern "C" void kernel_launch(void* const* d_in, const int* in_sizes, int n_in,
                              void* d_out, int out_size)
{
    const float* x1 = (const float*)d_in[0];
    const float* y1 = (const float*)d_in[1];
    float* out = (float*)d_out;

    dim3 grid(NQB, B_DIM, CSPLIT);   // (8, 8, 4) = 256 blocks x 8 warps
    chamfer_main<<<grid, TPB>>>(x1, y1, out);

    const float scale = 1.0f / (float)(B_DIM * N_PTS);
    pass2_kernel<<<(2 * B_DIM * N_PTS) / 256, 256>>>(out, scale);
}